// round 1
// baseline (speedup 1.0000x reference)
#include <cuda_runtime.h>
#include <cstdint>

// GaussianVoxel: 4 output levels [16,17,zr,64,64], zr in {1,2,4,64},
// concatenated flat into d_out (fp32). Z_COEFFS = (1,1,1,13).
// PAD=6, PATCH=13, SIZE=64, Z_MAX=64.
//
// Each thread writes one float4 (4 consecutive x). Value = g[gz,gy,gx] when
// (gz,gy,gx) inside the patch box centered per (b,j) coords, else 0.
// Pure streaming-store kernel: ~316 MB stores, negligible loads.

#define BATCH 16
#define JOINTS 17
#define NBJ (BATCH * JOINTS)
#define SIZE 64
#define PADC 6
#define PATCH 13

template<int ZRES, int ZC>
__global__ __launch_bounds__(256)
void gv_level_kernel(const float* __restrict__ coords,
                     const float* __restrict__ g,
                     float4* __restrict__ out)
{
    // total float4 elements for this level
    constexpr int TOT = NBJ * ZRES * SIZE * (SIZE / 4);
    int idx = blockIdx.x * blockDim.x + threadIdx.x;
    if (idx >= TOT) return;

    // decode: idx = ((bj*ZRES + z)*64 + y)*16 + x4   (all pow2 except bj)
    int x4 = idx & 15;
    int t  = idx >> 4;
    int y  = t & 63;
    t >>= 6;
    int z, bj;
    if (ZRES == 1)       { z = 0;       bj = t; }
    else                 { z = t & (ZRES - 1); bj = t >> (ZRES == 2 ? 1 : (ZRES == 4 ? 2 : 6)); }

    // coords for (b,j): 3 floats, fully L1-resident (3.3 KB table)
    float cx = __ldg(&coords[bj * 3 + 0]);
    float cy = __ldg(&coords[bj * 3 + 1]);
    float cz = __ldg(&coords[bj * 3 + 2]);
    int xi = (int)cx;
    int yi = (int)cy;
    // zidx = ceil(cz * ZRES / 64) - 1   (exact in fp32: cz integer-valued 0..63)
    int zidx = (int)ceilf(cz * ((float)ZRES * (1.0f / 64.0f))) - 1;

    constexpr int ZPAD = ZC / 2;
    int gz = z - zidx + ZPAD;
    int gy = y - yi + PADC;

    float4 v = make_float4(0.f, 0.f, 0.f, 0.f);
    if ((unsigned)gz < (unsigned)ZC && (unsigned)gy < (unsigned)PATCH) {
        const float* gp = g + (gz * PATCH + gy) * PATCH;
        int x0 = x4 * 4;
        float r[4];
        #pragma unroll
        for (int k = 0; k < 4; k++) {
            int gx = x0 + k - xi + PADC;
            r[k] = ((unsigned)gx < (unsigned)PATCH) ? __ldg(&gp[gx]) : 0.f;
        }
        v = make_float4(r[0], r[1], r[2], r[3]);
    }
    // streaming store: output (316 MB) >> L2, don't pollute
    __stcs(&out[idx], v);
}

extern "C" void kernel_launch(void* const* d_in, const int* in_sizes, int n_in,
                              void* d_out, int out_size)
{
    const float* coords = (const float*)d_in[0];
    const float* g0 = (const float*)d_in[1];
    const float* g1 = (const float*)d_in[2];
    const float* g2 = (const float*)d_in[3];
    const float* g3 = (const float*)d_in[4];
    float* out = (float*)d_out;

    // per-level element counts (fp32)
    constexpr long long L0 = (long long)NBJ * 1  * SIZE * SIZE;  // 1,114,112
    constexpr long long L1 = (long long)NBJ * 2  * SIZE * SIZE;  // 2,228,224
    constexpr long long L2 = (long long)NBJ * 4  * SIZE * SIZE;  // 4,456,448
    // L3 = NBJ * 64 * SIZE * SIZE

    float4* o0 = (float4*)(out);
    float4* o1 = (float4*)(out + L0);
    float4* o2 = (float4*)(out + L0 + L1);
    float4* o3 = (float4*)(out + L0 + L1 + L2);

    constexpr int T0 = NBJ * 1  * SIZE * (SIZE / 4);
    constexpr int T1 = NBJ * 2  * SIZE * (SIZE / 4);
    constexpr int T2 = NBJ * 4  * SIZE * (SIZE / 4);
    constexpr int T3 = NBJ * 64 * SIZE * (SIZE / 4);

    const int B = 256;
    gv_level_kernel<1, 1>  <<<(T0 + B - 1) / B, B>>>(coords, g0, o0);
    gv_level_kernel<2, 1>  <<<(T1 + B - 1) / B, B>>>(coords, g1, o1);
    gv_level_kernel<4, 1>  <<<(T2 + B - 1) / B, B>>>(coords, g2, o2);
    gv_level_kernel<64, 13><<<(T3 + B - 1) / B, B>>>(coords, g3, o3);
}